// round 15
// baseline (speedup 1.0000x reference)
#include <cuda_runtime.h>
#include <cuda.h>
#include <cuda_fp16.h>
#include <cstdint>

// ================================================================
// out[8192,4096] = A[8192,4096] (K-major) * W[4096,4096] (K-major)^T
// Persistent fp16 mma.sync GEMM with IN-KERNEL pipelined fp32->fp16
// conversion: k-panel p converted cooperatively by all CTAs during
// first-tile iteration p-10, published via panel counters
// (fence.proxy.async.global + red.release / ld.acquire), consumed
// by TMA producers. No separate pre-pass kernel.
// ================================================================

#define M_DIM 8192
#define N_DIM 4096
#define K_DIM 4096

#define BM 128
#define BN 256
#define BK 64                        // fp16 per K chunk = 128 B/row
#define STAGES 4
#define NCHUNK (K_DIM / BK)          // 64 chunks (=panels) per tile
#define NTILES ((M_DIM / BM) * (N_DIM / BN))   // 1024
#define NTHREADS 512
#define NWARPS 16
#define PRO_PANELS 10                // panels converted before mainloop

// conversion units: 8 floats each. A: 8192*8 = 65536, W: 4096*8 = 32768
#define A_UNITS 65536
#define TOT_UNITS 98304

#define A_STAGE_BYTES (BM * 128)     // 16384
#define B_STAGE_BYTES (BN * 128)     // 32768
#define STAGE_BYTES   (A_STAGE_BYTES + B_STAGE_BYTES)      // 49152
#define SMEM_TILE_OFF 1024
#define SMEM_BYTES    (SMEM_TILE_OFF + STAGES * STAGE_BYTES)  // 197632

__device__ __align__(1024) __half g_A[(size_t)M_DIM * K_DIM];
__device__ __align__(1024) __half g_B[(size_t)N_DIM * K_DIM];
__device__ uint32_t g_panel_done[NCHUNK];

__device__ __forceinline__ uint32_t smem_u32(const void* p) {
    uint32_t a;
    asm("{ .reg .u64 t; cvta.to.shared.u64 t, %1; cvt.u32.u64 %0, t; }" : "=r"(a) : "l"(p));
    return a;
}
#define MBARRIER_INIT(a, n) \
    asm volatile("mbarrier.init.shared.b64 [%0], %1;" :: "r"((uint32_t)(a)), "r"((uint32_t)(n)) : "memory")
#define MBARRIER_EXPECT_TX(a, b) \
    asm volatile("mbarrier.arrive.expect_tx.shared.b64 _, [%0], %1;" :: "r"((uint32_t)(a)), "r"((uint32_t)(b)) : "memory")
#define MBARRIER_ARRIVE(a) \
    asm volatile("mbarrier.arrive.shared.b64 _, [%0];" :: "r"((uint32_t)(a)) : "memory")

#define MBARRIER_WAIT_ACQ(a, ph) do {                                               \
    uint32_t _m = (uint32_t)(a), _p = (uint32_t)(ph), _d;                           \
    asm volatile("{\n\t.reg .pred p;\n\t"                                           \
        "mbarrier.try_wait.parity.acquire.cta.shared::cta.b64 p, [%1], %2;\n\t"     \
        "selp.b32 %0, 1, 0, p;\n\t}" : "=r"(_d) : "r"(_m), "r"(_p) : "memory");     \
    if (!_d) {                                                                       \
        asm volatile("{\n\t.reg .pred P1;\n\t"                                      \
            "WL_%=:\n\t"                                                            \
            "mbarrier.try_wait.parity.acquire.cta.shared::cta.b64 P1, [%0], %1, 0x989680;\n\t" \
            "@P1 bra.uni WD_%=;\n\t bra.uni WL_%=;\n\t WD_%=:\n\t}"                 \
            :: "r"(_m), "r"(_p) : "memory");                                        \
    }                                                                                \
} while (0)

#define MBARRIER_WAIT_RLX(a, ph) do {                                               \
    uint32_t _m = (uint32_t)(a), _p = (uint32_t)(ph), _d;                           \
    asm volatile("{\n\t.reg .pred p;\n\t"                                           \
        "mbarrier.try_wait.parity.relaxed.cta.shared::cta.b64 p, [%1], %2, 0x989680;\n\t" \
        "selp.b32 %0, 1, 0, p;\n\t}" : "=r"(_d) : "r"(_m), "r"(_p) : "memory");     \
    if (!_d) {                                                                       \
        asm volatile("{\n\t.reg .pred P1;\n\t"                                      \
            "WL_%=:\n\t"                                                            \
            "mbarrier.try_wait.parity.relaxed.cta.shared::cta.b64 P1, [%0], %1, 0x989680;\n\t" \
            "@P1 bra.uni WD_%=;\n\t bra.uni WL_%=;\n\t WD_%=:\n\t}"                 \
            :: "r"(_m), "r"(_p) : "memory");                                        \
    }                                                                                \
} while (0)

#define TMA_LOAD_2D(smem, map, c0, c1, mbar)                                        \
    asm volatile("cp.async.bulk.tensor.2d.shared::cta.global.tile.mbarrier::complete_tx::bytes " \
        "[%0], [%1, {%2, %3}], [%4];"                                               \
        :: "r"((uint32_t)(smem)), "l"(map), "r"((int)(c0)), "r"((int)(c1)),         \
           "r"((uint32_t)(mbar)) : "memory")

__device__ __forceinline__ void ldsm_x4(uint32_t r[4], uint32_t addr) {
    asm volatile("ldmatrix.sync.aligned.m8n8.x4.shared.b16 {%0,%1,%2,%3}, [%4];"
                 : "=r"(r[0]), "=r"(r[1]), "=r"(r[2]), "=r"(r[3]) : "r"(addr));
}
__device__ __forceinline__ void mma_f16(float c[4], const uint32_t a[4],
                                        uint32_t b0, uint32_t b1) {
    asm volatile(
        "mma.sync.aligned.m16n8k16.row.col.f32.f16.f16.f32 "
        "{%0,%1,%2,%3}, {%4,%5,%6,%7}, {%8,%9}, {%0,%1,%2,%3};"
        : "+f"(c[0]), "+f"(c[1]), "+f"(c[2]), "+f"(c[3])
        : "r"(a[0]), "r"(a[1]), "r"(a[2]), "r"(a[3]), "r"(b0), "r"(b1));
}

// convert this thread's share of k-panel `k` (A and W, 8 floats per unit)
__device__ __forceinline__ void convert_panel(
    const float* __restrict__ A_in, const float* __restrict__ W_in,
    int k, int slot, int stride)
{
    for (int u = slot; u < TOT_UNITS; u += stride) {
        const float* src;
        __half* dst;
        if (u < A_UNITS) {
            const size_t off = (size_t)(u >> 3) * K_DIM + k * 64 + (u & 7) * 8;
            src = A_in + off; dst = g_A + off;
        } else {
            const int v = u - A_UNITS;
            const size_t off = (size_t)(v >> 3) * K_DIM + k * 64 + (v & 7) * 8;
            src = W_in + off; dst = g_B + off;
        }
        float4 v0 = *reinterpret_cast<const float4*>(src);
        float4 v1 = *reinterpret_cast<const float4*>(src + 4);
        __half2 h0 = __floats2half2_rn(v0.x, v0.y);
        __half2 h1 = __floats2half2_rn(v0.z, v0.w);
        __half2 h2 = __floats2half2_rn(v1.x, v1.y);
        __half2 h3 = __floats2half2_rn(v1.z, v1.w);
        uint4 o;
        o.x = *reinterpret_cast<uint32_t*>(&h0);
        o.y = *reinterpret_cast<uint32_t*>(&h1);
        o.z = *reinterpret_cast<uint32_t*>(&h2);
        o.w = *reinterpret_cast<uint32_t*>(&h3);
        *reinterpret_cast<uint4*>(dst) = o;
    }
}

__device__ __forceinline__ void signal_panel(int p) {
    asm volatile("fence.proxy.async.global;" ::: "memory");
    asm volatile("red.release.gpu.global.add.u32 [%0], %1;"
                 :: "l"(&g_panel_done[p]), "r"(1u) : "memory");
}
__device__ __forceinline__ void wait_panel(int p, uint32_t target) {
    uint32_t c;
    do {
        asm volatile("ld.acquire.gpu.global.u32 %0, [%1];"
                     : "=r"(c) : "l"(&g_panel_done[p]) : "memory");
    } while (c < target);
}

__global__ void reset_kernel() {
    if (threadIdx.x < NCHUNK) g_panel_done[threadIdx.x] = 0;
}

extern __shared__ char smemc[];

// smem barriers: full[s] = sb + 16*s, empty[s] = sb + 16*s + 8
__global__ void __launch_bounds__(NTHREADS, 1) agg_gemm_kernel(
    const __grid_constant__ CUtensorMap tma_a,
    const __grid_constant__ CUtensorMap tma_b,
    const float* __restrict__ A_in,
    const float* __restrict__ W_in,
    float* __restrict__ out)
{
    const int t = threadIdx.x;
    const int wid = t >> 5;
    const int lane = t & 31;
    const int wm = wid & 3;          // warp M (0..3): 32 rows
    const int wn = wid >> 2;         // warp N (0..3): 64 cols
    const int g = lane >> 2;
    const int tig = lane & 3;

    const int bid = blockIdx.x;
    const int nsm = gridDim.x;
    const int cslot = bid * NTHREADS + t;
    const int cstride = nsm * NTHREADS;

    const uint32_t sb = smem_u32(smemc);
    const uint32_t tiles = sb + SMEM_TILE_OFF;

    if (t == 0) {
        #pragma unroll
        for (int s = 0; s < STAGES; s++) {
            MBARRIER_INIT(sb + 16 * s, 1);           // full: tx-based
            MBARRIER_INIT(sb + 16 * s + 8, NWARPS);  // empty: 16 warp arrives
        }
    }
    __syncthreads();

    // ---- conversion prologue: panels 0..PRO_PANELS-1 ----
    for (int p = 0; p < PRO_PANELS; p++)
        convert_panel(A_in, W_in, p, cslot, cstride);
    __syncthreads();
    if (t == 0)
        for (int p = 0; p < PRO_PANELS; p++) signal_panel(p);

    const int ntiles_mine = (NTILES - bid + nsm - 1) / nsm;
    const int gcl_end = ntiles_mine * NCHUNK;

    // produce flat local chunk f (waits for its k-panel to be converted)
    auto produce = [&](int f) {
        const int gt = bid + (f >> 6) * nsm;
        const int fm0 = (gt >> 4) * BM;
        const int fn0 = (gt & 15) * BN;
        const int st = f & (STAGES - 1);
        const int ph = 1 ^ ((f >> 2) & 1);
        const int kidx = f & (NCHUNK - 1);
        wait_panel(kidx, (uint32_t)nsm);
        const uint32_t fullb = sb + 16 * st;
        MBARRIER_WAIT_RLX(fullb + 8, ph);
        MBARRIER_EXPECT_TX(fullb, STAGE_BYTES);
        const uint32_t sbase = tiles + (uint32_t)st * STAGE_BYTES;
        TMA_LOAD_2D(sbase,                 &tma_a, kidx * BK, fm0, fullb);
        TMA_LOAD_2D(sbase + A_STAGE_BYTES, &tma_b, kidx * BK, fn0, fullb);
    };

    if (t == 0) {
        #pragma unroll
        for (int ps = 0; ps < STAGES - 1; ps++) produce(ps);
    }

    float acc[2][8][4];
    #pragma unroll
    for (int mi = 0; mi < 2; mi++)
        #pragma unroll
        for (int ni = 0; ni < 8; ni++)
            #pragma unroll
            for (int q = 0; q < 4; q++) acc[mi][ni][q] = 0.0f;

    const int lrow = lane & 15;
    const int lhi = lane >> 4;
    const int lsw = lane & 7;
    const uint32_t a_row_off = (uint32_t)(wm * 32 + lrow) * 128u;
    const uint32_t b_row_off = (uint32_t)A_STAGE_BYTES + (uint32_t)(wn * 64 + lrow) * 128u;

    const int ks0 = wid & 3;

    for (int ti = 0; ti < ntiles_mine; ti++) {
        const int gt = bid + ti * nsm;
        const int m0 = (gt >> 4) * BM;
        const int n0 = (gt & 15) * BN;
        const int gbase = ti * NCHUNK;

        for (int c = 0; c < NCHUNK; c++) {
            const int gcl = gbase + c;
            const int fetch = gcl + STAGES - 1;
            if (fetch < gcl_end && wid == (fetch & 15) && lane == 0) produce(fetch);

            const int cst = gcl & (STAGES - 1);
            const uint32_t fullb = sb + 16 * cst;
            MBARRIER_WAIT_ACQ(fullb, (gcl >> 2) & 1);

            const uint32_t sbase = tiles + (uint32_t)cst * STAGE_BYTES;

            #pragma unroll
            for (int kk = 0; kk < 4; kk++) {
                const int ks = (ks0 + kk) & 3;
                const uint32_t chunk = (uint32_t)(((ks * 2 + lhi) ^ lsw) * 16);
                uint32_t a[2][4];
                #pragma unroll
                for (int mi = 0; mi < 2; mi++)
                    ldsm_x4(a[mi], sbase + a_row_off + (uint32_t)(mi * 16 * 128) + chunk);
                uint32_t b[4][4];
                #pragma unroll
                for (int p = 0; p < 4; p++)
                    ldsm_x4(b[p], sbase + b_row_off + (uint32_t)(p * 16 * 128) + chunk);

                if (kk == 3 && lane == 0) MBARRIER_ARRIVE(fullb + 8);

                #pragma unroll
                for (int mi = 0; mi < 2; mi++) {
                    #pragma unroll
                    for (int p = 0; p < 4; p++) {
                        mma_f16(acc[mi][2 * p],     a[mi], b[p][0], b[p][2]);
                        mma_f16(acc[mi][2 * p + 1], a[mi], b[p][1], b[p][3]);
                    }
                }
            }

            // ---- embedded conversion pipeline (first tile only) ----
            if (ti == 0) {
                const int cp = c + PRO_PANELS;        // convert panel cp
                if (cp < NCHUNK) convert_panel(A_in, W_in, cp, cslot, cstride);
                const int sp = c + PRO_PANELS - 2;    // signal panel converted 2 iters ago
                if (c >= 2 && sp < NCHUNK) {
                    __syncthreads();
                    if (t == 0) signal_panel(sp);
                }
            }
        }

        // ---------------- epilogue (next tile's TMA already in flight) ----
        #pragma unroll
        for (int mi = 0; mi < 2; mi++) {
            const int row = m0 + wm * 32 + mi * 16 + g;
            #pragma unroll
            for (int ni = 0; ni < 8; ni++) {
                const int col = n0 + wn * 64 + ni * 8 + 2 * tig;
                float2 lo = make_float2(acc[mi][ni][0], acc[mi][ni][1]);
                float2 hi = make_float2(acc[mi][ni][2], acc[mi][ni][3]);
                *reinterpret_cast<float2*>(out + (size_t)row * N_DIM + col) = lo;
                *reinterpret_cast<float2*>(out + (size_t)(row + 8) * N_DIM + col) = hi;
                acc[mi][ni][0] = 0.0f; acc[mi][ni][1] = 0.0f;
                acc[mi][ni][2] = 0.0f; acc[mi][ni][3] = 0.0f;
            }
        }
    }
}

// ---------------- host ----------------
typedef CUresult (*PFN_EncodeTiled)(
    CUtensorMap*, CUtensorMapDataType, cuuint32_t, void*,
    const cuuint64_t*, const cuuint64_t*, const cuuint32_t*, const cuuint32_t*,
    CUtensorMapInterleave, CUtensorMapSwizzle, CUtensorMapL2promotion, CUtensorMapFloatOOBfill);

static void encode_2d_f16(PFN_EncodeTiled enc, CUtensorMap* map, void* ptr,
                          uint64_t dim0, uint64_t dim1, uint32_t box0, uint32_t box1) {
    cuuint64_t dims[2]    = {dim0, dim1};
    cuuint64_t strides[1] = {dim0 * sizeof(__half)};
    cuuint32_t box[2]     = {box0, box1};
    cuuint32_t estr[2]    = {1, 1};
    enc(map, CU_TENSOR_MAP_DATA_TYPE_FLOAT16, 2, ptr, dims, strides, box, estr,
        CU_TENSOR_MAP_INTERLEAVE_NONE, CU_TENSOR_MAP_SWIZZLE_128B,
        CU_TENSOR_MAP_L2_PROMOTION_L2_128B, CU_TENSOR_MAP_FLOAT_OOB_FILL_NONE);
}

extern "C" void kernel_launch(void* const* d_in, const int* in_sizes, int n_in,
                              void* d_out, int out_size) {
    const float* A_in = (const float*)d_in[0];   // [8,1024,4096] = [8192,4096]
    const float* W_in = (const float*)d_in[1];   // [4096,4096] K-major
    float* out = (float*)d_out;

    void *pA = nullptr, *pB = nullptr;
    cudaGetSymbolAddress(&pA, g_A);
    cudaGetSymbolAddress(&pB, g_B);

    void* fn = nullptr;
    cudaDriverEntryPointQueryResult st;
    cudaGetDriverEntryPointByVersion("cuTensorMapEncodeTiled", &fn, 12000,
                                     cudaEnableDefault, &st);
    PFN_EncodeTiled enc = (PFN_EncodeTiled)fn;

    CUtensorMap mapA, mapB;
    encode_2d_f16(enc, &mapA, pA, K_DIM, M_DIM, BK, BM);
    encode_2d_f16(enc, &mapB, pB, K_DIM, N_DIM, BK, BN);

    cudaFuncSetAttribute(agg_gemm_kernel,
                         cudaFuncAttributeMaxDynamicSharedMemorySize, SMEM_BYTES);

    int nsm = 148;
    cudaDeviceGetAttribute(&nsm, cudaDevAttrMultiProcessorCount, 0);

    reset_kernel<<<1, 64>>>();
    agg_gemm_kernel<<<nsm, NTHREADS, SMEM_BYTES>>>(mapA, mapB, A_in, W_in, out);
}

// round 16
// speedup vs baseline: 1.1190x; 1.1190x over previous
#include <cuda_runtime.h>
#include <cuda.h>
#include <cuda_fp16.h>
#include <cstdint>

// ================================================================
// out[8192,4096] = A[8192,4096] (K-major) * W[4096,4096] (K-major)^T
// fp16 mma.sync m16n8k16 + ldmatrix + TMA (SW128), 4-stage
// producer/consumer mbarrier pipeline. CTA 128x256, 512 threads,
// warp tile 32x64, ks rotation, rotating producer, early
// empty-arrive. Fused fp16 pre-pass with streaming cache hints.
// ================================================================

#define M_DIM 8192
#define N_DIM 4096
#define K_DIM 4096

#define BM 128
#define BN 256
#define BK 64                        // fp16 per K chunk = 128 B/row
#define STAGES 4
#define NCHUNK (K_DIM / BK)          // 64
#define NTHREADS 512
#define NWARPS 16

#define A_STAGE_BYTES (BM * 128)     // 16384
#define B_STAGE_BYTES (BN * 128)     // 32768
#define STAGE_BYTES   (A_STAGE_BYTES + B_STAGE_BYTES)      // 49152
#define SMEM_TILE_OFF 1024
#define SMEM_BYTES    (SMEM_TILE_OFF + STAGES * STAGE_BYTES)  // 197632

__device__ __align__(1024) __half g_A[(size_t)M_DIM * K_DIM];
__device__ __align__(1024) __half g_B[(size_t)N_DIM * K_DIM];

__device__ __forceinline__ uint32_t smem_u32(const void* p) {
    uint32_t a;
    asm("{ .reg .u64 t; cvta.to.shared.u64 t, %1; cvt.u32.u64 %0, t; }" : "=r"(a) : "l"(p));
    return a;
}
#define MBARRIER_INIT(a, n) \
    asm volatile("mbarrier.init.shared.b64 [%0], %1;" :: "r"((uint32_t)(a)), "r"((uint32_t)(n)) : "memory")
#define MBARRIER_EXPECT_TX(a, b) \
    asm volatile("mbarrier.arrive.expect_tx.shared.b64 _, [%0], %1;" :: "r"((uint32_t)(a)), "r"((uint32_t)(b)) : "memory")
#define MBARRIER_ARRIVE(a) \
    asm volatile("mbarrier.arrive.shared.b64 _, [%0];" :: "r"((uint32_t)(a)) : "memory")

#define MBARRIER_WAIT_ACQ(a, ph) do {                                               \
    uint32_t _m = (uint32_t)(a), _p = (uint32_t)(ph), _d;                           \
    asm volatile("{\n\t.reg .pred p;\n\t"                                           \
        "mbarrier.try_wait.parity.acquire.cta.shared::cta.b64 p, [%1], %2;\n\t"     \
        "selp.b32 %0, 1, 0, p;\n\t}" : "=r"(_d) : "r"(_m), "r"(_p) : "memory");     \
    if (!_d) {                                                                       \
        asm volatile("{\n\t.reg .pred P1;\n\t"                                      \
            "WL_%=:\n\t"                                                            \
            "mbarrier.try_wait.parity.acquire.cta.shared::cta.b64 P1, [%0], %1, 0x989680;\n\t" \
            "@P1 bra.uni WD_%=;\n\t bra.uni WL_%=;\n\t WD_%=:\n\t}"                 \
            :: "r"(_m), "r"(_p) : "memory");                                        \
    }                                                                                \
} while (0)

#define MBARRIER_WAIT_RLX(a, ph) do {                                               \
    uint32_t _m = (uint32_t)(a), _p = (uint32_t)(ph), _d;                           \
    asm volatile("{\n\t.reg .pred p;\n\t"                                           \
        "mbarrier.try_wait.parity.relaxed.cta.shared::cta.b64 p, [%1], %2, 0x989680;\n\t" \
        "selp.b32 %0, 1, 0, p;\n\t}" : "=r"(_d) : "r"(_m), "r"(_p) : "memory");     \
    if (!_d) {                                                                       \
        asm volatile("{\n\t.reg .pred P1;\n\t"                                      \
            "WL_%=:\n\t"                                                            \
            "mbarrier.try_wait.parity.relaxed.cta.shared::cta.b64 P1, [%0], %1, 0x989680;\n\t" \
            "@P1 bra.uni WD_%=;\n\t bra.uni WL_%=;\n\t WD_%=:\n\t}"                 \
            :: "r"(_m), "r"(_p) : "memory");                                        \
    }                                                                                \
} while (0)

#define TMA_LOAD_2D(smem, map, c0, c1, mbar)                                        \
    asm volatile("cp.async.bulk.tensor.2d.shared::cta.global.tile.mbarrier::complete_tx::bytes " \
        "[%0], [%1, {%2, %3}], [%4];"                                               \
        :: "r"((uint32_t)(smem)), "l"(map), "r"((int)(c0)), "r"((int)(c1)),         \
           "r"((uint32_t)(mbar)) : "memory")

__device__ __forceinline__ void ldsm_x4(uint32_t r[4], uint32_t addr) {
    asm volatile("ldmatrix.sync.aligned.m8n8.x4.shared.b16 {%0,%1,%2,%3}, [%4];"
                 : "=r"(r[0]), "=r"(r[1]), "=r"(r[2]), "=r"(r[3]) : "r"(addr));
}
__device__ __forceinline__ void mma_f16(float c[4], const uint32_t a[4],
                                        uint32_t b0, uint32_t b1) {
    asm volatile(
        "mma.sync.aligned.m16n8k16.row.col.f32.f16.f16.f32 "
        "{%0,%1,%2,%3}, {%4,%5,%6,%7}, {%8,%9}, {%0,%1,%2,%3};"
        : "+f"(c[0]), "+f"(c[1]), "+f"(c[2]), "+f"(c[3])
        : "r"(a[0]), "r"(a[1]), "r"(a[2]), "r"(a[3]), "r"(b0), "r"(b1));
}

// ---------------- fused pre-pass: fp32 -> fp16, streaming hints ----------------
__device__ __forceinline__ float4 ldg_nc_streaming(const float4* p) {
    float4 v;
    asm volatile("ld.global.nc.L1::no_allocate.v4.f32 {%0,%1,%2,%3}, [%4];"
                 : "=f"(v.x), "=f"(v.y), "=f"(v.z), "=f"(v.w) : "l"(p));
    return v;
}
__device__ __forceinline__ void stg_cs(uint4* p, uint4 v) {
    asm volatile("st.global.cs.v4.u32 [%0], {%1,%2,%3,%4};"
                 :: "l"(p), "r"(v.x), "r"(v.y), "r"(v.z), "r"(v.w));
}
__device__ __forceinline__ uint4 cvt8(float4 a, float4 b) {
    __half2 h0 = __floats2half2_rn(a.x, a.y);
    __half2 h1 = __floats2half2_rn(a.z, a.w);
    __half2 h2 = __floats2half2_rn(b.x, b.y);
    __half2 h3 = __floats2half2_rn(b.z, b.w);
    uint4 o;
    o.x = *reinterpret_cast<uint32_t*>(&h0);
    o.y = *reinterpret_cast<uint32_t*>(&h1);
    o.z = *reinterpret_cast<uint32_t*>(&h2);
    o.w = *reinterpret_cast<uint32_t*>(&h3);
    return o;
}

__global__ void __launch_bounds__(256) cvt_f16_fused(
    const float4* __restrict__ inA, const float4* __restrict__ inW,
    uint4* __restrict__ outA, uint4* __restrict__ outW,
    int n8A, int n8T)   // units of 8 floats
{
    int stride = gridDim.x * blockDim.x;
    for (int i = blockIdx.x * blockDim.x + threadIdx.x; i < n8T; i += stride) {
        if (i < n8A) {
            float4 v0 = ldg_nc_streaming(inA + 2 * i);
            float4 v1 = ldg_nc_streaming(inA + 2 * i + 1);
            stg_cs(outA + i, cvt8(v0, v1));
        } else {
            int j = i - n8A;
            float4 v0 = ldg_nc_streaming(inW + 2 * j);
            float4 v1 = ldg_nc_streaming(inW + 2 * j + 1);
            stg_cs(outW + j, cvt8(v0, v1));
        }
    }
}

extern __shared__ char smemc[];

// smem barriers: full[s] = sb + 16*s, empty[s] = sb + 16*s + 8
__global__ void __launch_bounds__(NTHREADS, 1) agg_gemm_kernel(
    const __grid_constant__ CUtensorMap tma_a,
    const __grid_constant__ CUtensorMap tma_b,
    float* __restrict__ out)
{
    const int t = threadIdx.x;
    const int wid = t >> 5;
    const int lane = t & 31;
    const int wm = wid & 3;          // warp M (0..3): 32 rows
    const int wn = wid >> 2;         // warp N (0..3): 64 cols
    const int g = lane >> 2;
    const int tig = lane & 3;

    const int m0 = blockIdx.y * BM;
    const int n0 = blockIdx.x * BN;

    const uint32_t sb = smem_u32(smemc);
    const uint32_t tiles = sb + SMEM_TILE_OFF;

    if (t == 0) {
        #pragma unroll
        for (int s = 0; s < STAGES; s++) {
            MBARRIER_INIT(sb + 16 * s, 1);           // full: tx-based
            MBARRIER_INIT(sb + 16 * s + 8, NWARPS);  // empty: 16 warp arrives
        }
    }
    __syncthreads();

    // produce chunk f: stage = f % STAGES, empty-wait parity = 1 ^ ((f/STAGES)&1)
    auto produce = [&](int f) {
        const int st = f & (STAGES - 1);
        const int ph = 1 ^ ((f >> 2) & 1);
        const uint32_t fullb = sb + 16 * st;
        MBARRIER_WAIT_RLX(fullb + 8, ph);
        MBARRIER_EXPECT_TX(fullb, STAGE_BYTES);
        const uint32_t sbase = tiles + (uint32_t)st * STAGE_BYTES;
        TMA_LOAD_2D(sbase,                 &tma_a, f * BK, m0, fullb);
        TMA_LOAD_2D(sbase + A_STAGE_BYTES, &tma_b, f * BK, n0, fullb);
    };

    if (t == 0) {
        #pragma unroll
        for (int ps = 0; ps < STAGES - 1; ps++) produce(ps);
    }

    float acc[2][8][4];
    #pragma unroll
    for (int mi = 0; mi < 2; mi++)
        #pragma unroll
        for (int ni = 0; ni < 8; ni++)
            #pragma unroll
            for (int q = 0; q < 4; q++) acc[mi][ni][q] = 0.0f;

    // ldmatrix: row = base + (lane&15); chunk16 ^= (row & 7)
    const int lrow = lane & 15;
    const int lhi = lane >> 4;
    const int lsw = lane & 7;
    const uint32_t a_row_off = (uint32_t)(wm * 32 + lrow) * 128u;
    const uint32_t b_row_off = (uint32_t)A_STAGE_BYTES + (uint32_t)(wn * 64 + lrow) * 128u;

    const int ks0 = wid & 3;         // ks rotation start per warp

    int cstage = 0, cphase = 0;

    for (int c = 0; c < NCHUNK; c++) {
        // rotating producer: warp (fetch & 15) issues the TMA for chunk fetch
        const int fetch = c + STAGES - 1;
        if (fetch < NCHUNK && wid == (fetch & 15) && lane == 0) produce(fetch);

        const uint32_t fullb = sb + 16 * cstage;
        MBARRIER_WAIT_ACQ(fullb, cphase);

        const uint32_t sbase = tiles + (uint32_t)cstage * STAGE_BYTES;

        #pragma unroll
        for (int kk = 0; kk < 4; kk++) {
            const int ks = (ks0 + kk) & 3;
            const uint32_t chunk = (uint32_t)(((ks * 2 + lhi) ^ lsw) * 16);
            uint32_t a[2][4];
            #pragma unroll
            for (int mi = 0; mi < 2; mi++)
                ldsm_x4(a[mi], sbase + a_row_off + (uint32_t)(mi * 16 * 128) + chunk);
            uint32_t b[4][4];
            #pragma unroll
            for (int p = 0; p < 4; p++)
                ldsm_x4(b[p], sbase + b_row_off + (uint32_t)(p * 16 * 128) + chunk);

            // after the final slice's LDSMs this warp is done READING the
            // stage -> release it before the trailing HMMAs
            if (kk == 3 && lane == 0) MBARRIER_ARRIVE(fullb + 8);

            #pragma unroll
            for (int mi = 0; mi < 2; mi++) {
                #pragma unroll
                for (int p = 0; p < 4; p++) {
                    mma_f16(acc[mi][2 * p],     a[mi], b[p][0], b[p][2]);
                    mma_f16(acc[mi][2 * p + 1], a[mi], b[p][1], b[p][3]);
                }
            }
        }

        if (++cstage == STAGES) { cstage = 0; cphase ^= 1; }
    }

    // ---------------- epilogue ----------------
    #pragma unroll
    for (int mi = 0; mi < 2; mi++) {
        const int row = m0 + wm * 32 + mi * 16 + g;
        #pragma unroll
        for (int ni = 0; ni < 8; ni++) {
            const int col = n0 + wn * 64 + ni * 8 + 2 * tig;
            float2 lo = make_float2(acc[mi][ni][0], acc[mi][ni][1]);
            float2 hi = make_float2(acc[mi][ni][2], acc[mi][ni][3]);
            *reinterpret_cast<float2*>(out + (size_t)row * N_DIM + col) = lo;
            *reinterpret_cast<float2*>(out + (size_t)(row + 8) * N_DIM + col) = hi;
        }
    }
}

// ---------------- host ----------------
typedef CUresult (*PFN_EncodeTiled)(
    CUtensorMap*, CUtensorMapDataType, cuuint32_t, void*,
    const cuuint64_t*, const cuuint64_t*, const cuuint32_t*, const cuuint32_t*,
    CUtensorMapInterleave, CUtensorMapSwizzle, CUtensorMapL2promotion, CUtensorMapFloatOOBfill);

static void encode_2d_f16(PFN_EncodeTiled enc, CUtensorMap* map, void* ptr,
                          uint64_t dim0, uint64_t dim1, uint32_t box0, uint32_t box1) {
    cuuint64_t dims[2]    = {dim0, dim1};
    cuuint64_t strides[1] = {dim0 * sizeof(__half)};
    cuuint32_t box[2]     = {box0, box1};
    cuuint32_t estr[2]    = {1, 1};
    enc(map, CU_TENSOR_MAP_DATA_TYPE_FLOAT16, 2, ptr, dims, strides, box, estr,
        CU_TENSOR_MAP_INTERLEAVE_NONE, CU_TENSOR_MAP_SWIZZLE_128B,
        CU_TENSOR_MAP_L2_PROMOTION_L2_128B, CU_TENSOR_MAP_FLOAT_OOB_FILL_NONE);
}

extern "C" void kernel_launch(void* const* d_in, const int* in_sizes, int n_in,
                              void* d_out, int out_size) {
    const float* A_in = (const float*)d_in[0];   // [8,1024,4096] = [8192,4096]
    const float* W_in = (const float*)d_in[1];   // [4096,4096] K-major
    float* out = (float*)d_out;

    void *pA = nullptr, *pB = nullptr;
    cudaGetSymbolAddress(&pA, g_A);
    cudaGetSymbolAddress(&pB, g_B);

    void* fn = nullptr;
    cudaDriverEntryPointQueryResult st;
    cudaGetDriverEntryPointByVersion("cuTensorMapEncodeTiled", &fn, 12000,
                                     cudaEnableDefault, &st);
    PFN_EncodeTiled enc = (PFN_EncodeTiled)fn;

    CUtensorMap mapA, mapB;
    encode_2d_f16(enc, &mapA, pA, K_DIM, M_DIM, BK, BM);
    encode_2d_f16(enc, &mapB, pB, K_DIM, N_DIM, BK, BN);

    cudaFuncSetAttribute(agg_gemm_kernel,
                         cudaFuncAttributeMaxDynamicSharedMemorySize, SMEM_BYTES);

    const int n8A = (int)(((size_t)M_DIM * K_DIM) / 8);
    const int n8W = (int)(((size_t)N_DIM * K_DIM) / 8);
    cvt_f16_fused<<<2368, 256>>>((const float4*)A_in, (const float4*)W_in,
                                 (uint4*)pA, (uint4*)pB, n8A, n8A + n8W);

    dim3 grid(N_DIM / BN, M_DIM / BM);   // (16, 64)
    agg_gemm_kernel<<<grid, NTHREADS, SMEM_BYTES>>>(mapA, mapB, out);
}